// round 5
// baseline (speedup 1.0000x reference)
#include <cuda_runtime.h>
#include <cuda_fp16.h>
#include <cstdint>

// AnomalyAttention, sm_103, fp16 HMMA split GEMMs, 64-row tiles, 2 CTAs/SM.
// B=32 L=S=512 H=8 E=64.

#define Bn 32
#define Ln 512
#define Hn 8
#define En 64
#define Sn 512
#define HE (Hn*En)
#define TM 64   // L rows per CTA

static constexpr size_t VOUT_ELEMS = (size_t)Bn * Ln * Hn * En;  // 8388608
static constexpr size_t SER_ELEMS  = (size_t)Bn * Hn * Ln * Sn;  // 67108864

// ---- smem layout (bytes) ----
#define QH_OFF 0        // 64x64 fp16 SW128 (8192)
#define QL_OFF 8192     // (8192)
#define KH_OFF 16384    // 128x64 fp16 K/V chunk hi (16384)
#define KL_OFF 32768    // chunk lo (16384)
#define P_OFF  49152    // 64 rows x 1024B fp16, swizzled (65536)
#define RS_OFF 114688   // rowsum[2][64] f32 (512)
#define INV_OFF 115200  // inv[64] f32 (256)
#define SMEM_BYTES 115456

#define SWZ(o) ((o) ^ ((((unsigned)(o)) >> 3) & 0x70u))
#define PADDR(row, b0) (P_OFF + (unsigned)(row) * 1024u + ((unsigned)(b0) & ~127u) \
                        + (((unsigned)(b0) & 127u) ^ (((unsigned)(row) & 7u) << 4)))

__device__ __forceinline__ uint32_t smem_u32(const void* p) {
    uint32_t a;
    asm("{ .reg .u64 t; cvta.to.shared.u64 t, %1; cvt.u32.u64 %0, t; }" : "=r"(a) : "l"(p));
    return a;
}
__device__ __forceinline__ void ldm_x4(uint32_t a, uint32_t r[4]) {
    asm volatile("ldmatrix.sync.aligned.m8n8.x4.shared.b16 {%0,%1,%2,%3}, [%4];"
        : "=r"(r[0]), "=r"(r[1]), "=r"(r[2]), "=r"(r[3]) : "r"(a));
}
__device__ __forceinline__ void ldm_x4t(uint32_t a, uint32_t r[4]) {
    asm volatile("ldmatrix.sync.aligned.m8n8.x4.trans.shared.b16 {%0,%1,%2,%3}, [%4];"
        : "=r"(r[0]), "=r"(r[1]), "=r"(r[2]), "=r"(r[3]) : "r"(a));
}
__device__ __forceinline__ void mma_f16(float c[4], const uint32_t a[4],
                                        uint32_t b0, uint32_t b1) {
    asm volatile("mma.sync.aligned.m16n8k16.row.col.f32.f16.f16.f32 "
        "{%0,%1,%2,%3}, {%4,%5,%6,%7}, {%8,%9}, {%0,%1,%2,%3};"
        : "+f"(c[0]), "+f"(c[1]), "+f"(c[2]), "+f"(c[3])
        : "r"(a[0]), "r"(a[1]), "r"(a[2]), "r"(a[3]), "r"(b0), "r"(b1));
}
__device__ __forceinline__ uint32_t pkh2(float lo, float hi) {
    __half2 t = __floats2half2_rn(lo, hi);
    return *reinterpret_cast<uint32_t*>(&t);
}
__device__ __forceinline__ void split2(float x, float y, uint32_t& hi, uint32_t& lo) {
    __half2 h = __floats2half2_rn(x, y);
    float2 hf = __half22float2(h);
    hi = *reinterpret_cast<uint32_t*>(&h);
    __half2 l = __floats2half2_rn(x - hf.x, y - hf.y);
    lo = *reinterpret_cast<uint32_t*>(&l);
}

// load [ROWSx64] f32 (row stride HE), split into hi/lo SW128 fp16 tiles
template<int ROWS>
__device__ __forceinline__ void commit(const float* __restrict__ g, char* sm, int tid,
                                       unsigned hoff, unsigned loff, float scale) {
#pragma unroll
    for (int idx = tid; idx < ROWS * 8; idx += 256) {
        int row = idx >> 3, cp = idx & 7;
        const float4* s = (const float4*)(g + (size_t)row * HE + cp * 8);
        float4 a = s[0], b = s[1];
        uint4 hi, lo;
        split2(a.x * scale, a.y * scale, hi.x, lo.x);
        split2(a.z * scale, a.w * scale, hi.y, lo.y);
        split2(b.x * scale, b.y * scale, hi.z, lo.z);
        split2(b.z * scale, b.w * scale, hi.w, lo.w);
        unsigned rel = row * 128 + cp * 16;
        *(uint4*)(sm + hoff + SWZ(rel)) = hi;
        *(uint4*)(sm + loff + SWZ(rel)) = lo;
    }
}

__global__ __launch_bounds__(256, 2)
void anomaly_attn_s64(const float* __restrict__ Q, const float* __restrict__ K,
                      const float* __restrict__ V, const float* __restrict__ Sg,
                      float* __restrict__ out)
{
    extern __shared__ char sm[];
    const uint32_t smu = smem_u32(sm);
    float* RS  = (float*)(sm + RS_OFF);
    float* INV = (float*)(sm + INV_OFF);

    const int tid  = threadIdx.x;
    const int wid  = tid >> 5;
    const int lane = tid & 31;
    const int g    = lane >> 2;
    const int t    = lane & 3;
    const int mw   = wid & 3;      // m-tile (16 rows)
    const int nw   = wid >> 2;     // n-slice
    const int m0   = mw * 16;

    const int tile = blockIdx.x & 7;
    const int h    = (blockIdx.x >> 3) & 7;
    const int b    = blockIdx.x >> 6;
    const int l0   = tile * TM;

    const size_t qkv = ((size_t)b * Ln) * HE + (size_t)h * En;
    const size_t rowBaseSP = (size_t)(b * Hn + h) * Ln + l0;

    // ---- Q load/split (pre-scaled 1/8) ----
    commit<TM>(Q + qkv + (size_t)l0 * HE, sm, tid, QH_OFF, QL_OFF, 0.125f);
    __syncthreads();

    // ---- Q A-fragments hi & lo ----
    uint32_t ahi[4][4], alo[4][4];
    {
        int r = m0 + (lane & 15);
        int ch = lane >> 4;
#pragma unroll
        for (int kk = 0; kk < 4; ++kk) {
            unsigned rel = (unsigned)r * 128 + kk * 32 + ch * 16;
            ldm_x4(smu + QH_OFF + SWZ(rel), ahi[kk]);
            ldm_x4(smu + QL_OFF + SWZ(rel), alo[kk]);
        }
    }

    // ---- QK^T over 4 S-chunks of 128; warp covers 16 rows x 64 cols ----
    float rs0 = 0.f, rs1 = 0.f;
#pragma unroll 1
    for (int c = 0; c < 4; ++c) {
        commit<128>(K + qkv + (size_t)(c * 128) * HE, sm, tid, KH_OFF, KL_OFF, 1.0f);
        __syncthreads();

        float acc[8][4];
#pragma unroll
        for (int i = 0; i < 8; ++i) { acc[i][0]=0.f; acc[i][1]=0.f; acc[i][2]=0.f; acc[i][3]=0.f; }
#pragma unroll
        for (int kk = 0; kk < 4; ++kk) {
#pragma unroll
            for (int jj = 0; jj < 4; ++jj) {
                uint32_t bhi[4], blo[4];
                int r = nw * 64 + jj * 16 + (lane & 15);
                unsigned rel = (unsigned)r * 128 + kk * 32 + (lane >> 4) * 16;
                ldm_x4(smu + KH_OFF + SWZ(rel), bhi);
                ldm_x4(smu + KL_OFF + SWZ(rel), blo);
                mma_f16(acc[2 * jj],     ahi[kk], bhi[0], bhi[2]);
                mma_f16(acc[2 * jj],     ahi[kk], blo[0], blo[2]);
                mma_f16(acc[2 * jj],     alo[kk], bhi[0], bhi[2]);
                mma_f16(acc[2 * jj + 1], ahi[kk], bhi[1], bhi[3]);
                mma_f16(acc[2 * jj + 1], ahi[kk], blo[1], blo[3]);
                mma_f16(acc[2 * jj + 1], alo[kk], bhi[1], bhi[3]);
            }
        }
        // exp -> P fp16, rowsum partials
        int row0 = m0 + g, row1 = m0 + 8 + g;
#pragma unroll
        for (int nt = 0; nt < 8; ++nt) {
            float e0 = __expf(acc[nt][0]), e1 = __expf(acc[nt][1]);
            float e2 = __expf(acc[nt][2]), e3 = __expf(acc[nt][3]);
            rs0 += e0 + e1; rs1 += e2 + e3;
            unsigned b0 = (unsigned)(c * 128 + nw * 64 + nt * 8 + 2 * t) * 2;
            *(uint32_t*)(sm + PADDR(row0, b0)) = pkh2(e0, e1);
            *(uint32_t*)(sm + PADDR(row1, b0)) = pkh2(e2, e3);
        }
        __syncthreads();
    }
    rs0 += __shfl_xor_sync(0xffffffffu, rs0, 1);
    rs0 += __shfl_xor_sync(0xffffffffu, rs0, 2);
    rs1 += __shfl_xor_sync(0xffffffffu, rs1, 1);
    rs1 += __shfl_xor_sync(0xffffffffu, rs1, 2);
    if (t == 0) { RS[nw * 64 + m0 + g] = rs0; RS[nw * 64 + m0 + 8 + g] = rs1; }
    __syncthreads();
    if (tid < TM) INV[tid] = 1.0f / (RS[tid] + RS[64 + tid]);
    __syncthreads();

    // ---- series write: warp rows wid*8..+7, full 512 cols ----
    {
        float* serB = out + VOUT_ELEMS;
#pragma unroll 1
        for (int rr = 0; rr < 8; ++rr) {
            int row = wid * 8 + rr;
            float iv = INV[row];
            float* srow = serB + (rowBaseSP + row) * (size_t)Sn;
#pragma unroll
            for (int j = 0; j < 4; ++j) {
                int col = j * 128 + lane * 4;
                uint2 pv = *(uint2*)(sm + PADDR(row, (unsigned)col * 2));
                __half2 p0 = *reinterpret_cast<__half2*>(&pv.x);
                __half2 p1 = *reinterpret_cast<__half2*>(&pv.y);
                float4 o;
                o.x = __half2float(p0.x) * iv;
                o.y = __half2float(p0.y) * iv;
                o.z = __half2float(p1.x) * iv;
                o.w = __half2float(p1.y) * iv;
                *(float4*)(srow + col) = o;
            }
        }
    }

    // ---- AV: P(64x512) @ V(512x64); warp covers 16 rows x 32 E-cols ----
    float oacc[4][4];
#pragma unroll
    for (int i = 0; i < 4; ++i) { oacc[i][0]=0.f; oacc[i][1]=0.f; oacc[i][2]=0.f; oacc[i][3]=0.f; }
#pragma unroll 1
    for (int c = 0; c < 4; ++c) {
        __syncthreads();   // prev chunk consumed / P reads (series) done before overwrite? (P untouched; KH/KL reads done)
        commit<128>(V + qkv + (size_t)(c * 128) * HE, sm, tid, KH_OFF, KL_OFF, 1.0f);
        __syncthreads();
#pragma unroll
        for (int kl = 0; kl < 8; ++kl) {
            int ks = c * 8 + kl;
            uint32_t af2[4];
            ldm_x4(smu + PADDR(m0 + (lane & 15), ks * 32 + (lane >> 4) * 16), af2);
#pragma unroll
            for (int et = 0; et < 2; ++et) {
                uint32_t bhi[4], blo[4];
                int s = kl * 16 + (lane & 15);
                unsigned rel = (unsigned)s * 128 + nw * 64 + et * 32 + (lane >> 4) * 16;
                ldm_x4t(smu + KH_OFF + SWZ(rel), bhi);
                ldm_x4t(smu + KL_OFF + SWZ(rel), blo);
                mma_f16(oacc[2 * et],     af2, bhi[0], bhi[1]);
                mma_f16(oacc[2 * et],     af2, blo[0], blo[1]);
                mma_f16(oacc[2 * et + 1], af2, bhi[2], bhi[3]);
                mma_f16(oacc[2 * et + 1], af2, blo[2], blo[3]);
            }
        }
    }

    // ---- V_out = oacc * inv, layout [B,L,H,E] ----
    {
        int r0 = m0 + g, r1 = m0 + 8 + g;
        float iv0 = INV[r0], iv1 = INV[r1];
        float* o0 = out + (((size_t)(b * Ln + l0 + r0)) * Hn + h) * En + nw * 32;
        float* o1 = out + (((size_t)(b * Ln + l0 + r1)) * Hn + h) * En + nw * 32;
#pragma unroll
        for (int k = 0; k < 4; ++k) {
            int e = k * 8 + 2 * t;
            float2 v0 = { oacc[k][0] * iv0, oacc[k][1] * iv0 };
            float2 v1 = { oacc[k][2] * iv1, oacc[k][3] * iv1 };
            *(float2*)(o0 + e) = v0;
            *(float2*)(o1 + e) = v1;
        }
    }

    // ---- prior: warp rows wid*8..+7 ----
    {
        float sigl = 1.f;
        if (lane < 8) {
            int row = wid * 8 + lane;
            float x = Sg[(size_t)(b * Ln + l0 + row) * Hn + h];
            double sgm = 1.0 / (1.0 + exp(-5.0 * (double)x));
            float sgf = (float)sgm + 1e-5f;
            float p3 = (float)exp((double)sgf * 1.0986122886681098);
            sigl = p3 - 1.0f;
        }
        const double s2pi_d = 2.506628274631000502415765284811;
        const float  s2pi_f = (float)s2pi_d;
        const float  inv_sqrt_2pi = (float)(1.0 / (double)s2pi_f);
        float* priB = out + VOUT_ELEMS + SER_ELEMS;
#pragma unroll 1
        for (int rr = 0; rr < 8; ++rr) {
            int row = wid * 8 + rr;
            float sig = __shfl_sync(0xffffffffu, sigl, rr);
            float amp = inv_sqrt_2pi / sig;
            float nb  = -0.5f / (sig * sig);
            int l = l0 + row;
            float* prow = priB + (rowBaseSP + row) * (size_t)Sn;
#pragma unroll
            for (int j = 0; j < 4; ++j) {
                int s0 = j * 128 + lane * 4;
                float d0 = (float)(l - s0);
                float4 o;
                o.x = amp * __expf(nb * d0 * d0);
                float d1 = d0 - 1.f;
                o.y = amp * __expf(nb * d1 * d1);
                float d2 = d0 - 2.f;
                o.z = amp * __expf(nb * d2 * d2);
                float d3 = d0 - 3.f;
                o.w = amp * __expf(nb * d3 * d3);
                *(float4*)(prow + s0) = o;
            }
        }
    }
}

extern "C" void kernel_launch(void* const* d_in, const int* in_sizes, int n_in,
                              void* d_out, int out_size)
{
    const float* Q  = (const float*)d_in[0];
    const float* K  = (const float*)d_in[1];
    const float* V  = (const float*)d_in[2];
    const float* Sg = (const float*)d_in[3];
    float* out = (float*)d_out;

    cudaFuncSetAttribute(anomaly_attn_s64,
                         cudaFuncAttributeMaxDynamicSharedMemorySize, SMEM_BYTES);
    dim3 grid(Bn * Hn * (Ln / TM));   // 2048 CTAs
    anomaly_attn_s64<<<grid, 256, SMEM_BYTES>>>(Q, K, V, Sg, out);
}